// round 14
// baseline (speedup 1.0000x reference)
#include <cuda_runtime.h>

#define BATCH 131072
#define NCH 16
#define NK 15
#define NZ 256
#define NCOUT 10
#define MAXREG 128
#define VOCAB 1024

typedef unsigned long long u64;

// ---------------- scratch (device globals; no allocation) ----------------
__device__ unsigned       g_seen[NCH][1024];     // built by k_masks, read+zeroed by k_tc tables blocks
__device__ unsigned char  g_rmap[NCH][32768];    // mask -> region id (observed entries valid this launch)
__device__ unsigned       g_maskw[BATCH * 8];    // packed masks: channel pair per u32
__device__ int            g_cnt[NCH];            // #distinct masks per channel (<=121)
__device__ float          g_zreg[NCH][MAXREG][NZ];       // per-region half z-row
__device__ unsigned char  g_cross[8][MAXREG][MAXREG];    // argmax index per (c8, rA, rB)
__device__ volatile int   g_flag[NCH];           // per-channel tables-done; reset by k_main

// ================= K1: sign masks — 2 elements/thread, constants amortized (R11) ========
#define K1_BLK 256
#define K1_THR 256
#define K1_SMEM (8192 + 8192 + 1920 + 960 + 65536)   // 84800 B -> 2 blocks/SM

__global__ void __launch_bounds__(K1_THR, 2) k_masks(
    const int* __restrict__ x, const float* __restrict__ lenLUT,
    const float* __restrict__ ipdLUT, const float* __restrict__ S,
    const float* __restrict__ T)
{
    extern __shared__ char dyn[];
    float2*     sLen = (float2*)dyn;                     // 8 KB
    float2*     sIpd = (float2*)(dyn + 8192);            // 8 KB
    ulonglong2* sSP  = (ulonglong2*)(dyn + 16384);       // 120 x {S0p, S1p}  (1920 B)
    u64*        sC   = (u64*)(dyn + 16384 + 1920);       // 120 x packed (-T-1e-4) (960 B)
    unsigned*   filt = (unsigned*)(dyn + 16384 + 2880);  // 64 KB block-local seen filter

    const int tid = threadIdx.x;
    for (int i = tid; i < VOCAB; i += K1_THR) {
        sLen[i] = ((const float2*)lenLUT)[i];
        sIpd[i] = ((const float2*)ipdLUT)[i];
    }
    if (tid < 120) {                                     // pack per-pair plane constants
        int i = tid / NK, k = tid % NK;
        int cA = 2 * i, cB = 2 * i + 1;
        u64 s0 = ((u64)__float_as_uint(S[cB * 30 + k])      << 32) | __float_as_uint(S[cA * 30 + k]);
        u64 s1 = ((u64)__float_as_uint(S[cB * 30 + 15 + k]) << 32) | __float_as_uint(S[cA * 30 + 15 + k]);
        float cAv = -T[cA * NK + k] - 1e-4f;
        float cBv = -T[cB * NK + k] - 1e-4f;
        sSP[tid] = make_ulonglong2(s0, s1);
        sC[tid]  = ((u64)__float_as_uint(cBv) << 32) | __float_as_uint(cAv);
    }
    for (int i = tid; i < NCH * 1024; i += K1_THR) filt[i] = 0u;
    __syncthreads();

    const int b0 = blockIdx.x * K1_THR + tid;            // 65536 threads, 2 elems each
    const int b1 = b0 + 65536;
    const int4* xp0 = (const int4*)x + (size_t)b0 * 8;
    const int4* xp1 = (const int4*)x + (size_t)b1 * 8;

    unsigned w0[8], w1[8];
    #pragma unroll
    for (int i = 0; i < 8; i++) {
        int4 xv0 = __ldg(&xp0[i]);
        int4 xv1 = __ldg(&xp1[i]);

        float2 lA0 = sLen[xv0.x], pA0 = sIpd[xv0.y];
        float2 lB0 = sLen[xv0.z], pB0 = sIpd[xv0.w];
        float2 lA1 = sLen[xv1.x], pA1 = sIpd[xv1.y];
        float2 lB1 = sLen[xv1.z], pB1 = sIpd[xv1.w];

        u64 e0p0, e1p0, e0p1, e1p1;
        {
            float a = lA0.x + pA0.x, b = lB0.x + pB0.x;
            asm("mov.b64 %0, {%1, %2};" : "=l"(e0p0) : "f"(a), "f"(b));
            float c = lA0.y + pA0.y, d = lB0.y + pB0.y;
            asm("mov.b64 %0, {%1, %2};" : "=l"(e1p0) : "f"(c), "f"(d));
            float e = lA1.x + pA1.x, f = lB1.x + pB1.x;
            asm("mov.b64 %0, {%1, %2};" : "=l"(e0p1) : "f"(e), "f"(f));
            float g = lA1.y + pA1.y, h = lB1.y + pB1.y;
            asm("mov.b64 %0, {%1, %2};" : "=l"(e1p1) : "f"(g), "f"(h));
        }

        unsigned pair0 = 0, pair1 = 0;
        #pragma unroll
        for (int k = 0; k < NK; k++) {
            ulonglong2 sp = sSP[i * NK + k];             // LDS.128: S0p, S1p
            u64        cc = sC[i * NK + k];              // LDS.64
            u64 t0, y0, t1, y1;
            asm("fma.rn.f32x2 %0, %1, %2, %3;" : "=l"(t0) : "l"(e0p0), "l"(sp.x), "l"(cc));
            asm("fma.rn.f32x2 %0, %1, %2, %3;" : "=l"(t1) : "l"(e0p1), "l"(sp.x), "l"(cc));
            asm("fma.rn.f32x2 %0, %1, %2, %3;" : "=l"(y0) : "l"(e1p0), "l"(sp.y), "l"(t0));
            asm("fma.rn.f32x2 %0, %1, %2, %3;" : "=l"(y1) : "l"(e1p1), "l"(sp.y), "l"(t1));
            unsigned lo0 = (unsigned)y0, hi0 = (unsigned)(y0 >> 32);
            unsigned lo1 = (unsigned)y1, hi1 = (unsigned)(y1 >> 32);
            pair0 |= ((lo0 >> 31) << k) | ((hi0 >> 31) << (16 + k));  // bit set <=> y<0
            pair1 |= ((lo1 >> 31) << k) | ((hi1 >> 31) << (16 + k));
        }
        w0[i] = pair0;
        w1[i] = pair1;
    }

    {
        uint4* mp0 = (uint4*)&g_maskw[(size_t)b0 * 8];
        mp0[0] = make_uint4(w0[0], w0[1], w0[2], w0[3]);
        mp0[1] = make_uint4(w0[4], w0[5], w0[6], w0[7]);
        uint4* mp1 = (uint4*)&g_maskw[(size_t)b1 * 8];
        mp1[0] = make_uint4(w1[0], w1[1], w1[2], w1[3]);
        mp1[1] = make_uint4(w1[4], w1[5], w1[6], w1[7]);
    }

    // seen-set update for both elements (block filter -> rare global atomic)
    #pragma unroll
    for (int i = 0; i < 8; i++) {
        #pragma unroll
        for (int h = 0; h < 2; h++) {
            unsigned m0 = (w0[i] >> (16 * h)) & 0xffffu;
            unsigned m1 = (w1[i] >> (16 * h)) & 0xffffu;
            int c = 2 * i + h;
            unsigned wd0 = c * 1024 + (m0 >> 5), bt0 = 1u << (m0 & 31);
            if (!(filt[wd0] & bt0)) {
                unsigned old = atomicOr(&filt[wd0], bt0);
                if (!(old & bt0)) atomicOr((unsigned*)&g_seen[c][m0 >> 5], bt0);
            }
            unsigned wd1 = c * 1024 + (m1 >> 5), bt1 = 1u << (m1 & 31);
            if (!(filt[wd1] & bt1)) {
                unsigned old = atomicOr(&filt[wd1], bt1);
                if (!(old & bt1)) atomicOr((unsigned*)&g_seen[c][m1 >> 5], bt1);
            }
        }
    }
}

// ================= K2: fused tables + cross (R13, unchanged) =================
__global__ void __launch_bounds__(1024, 2) k_tc(const float* __restrict__ H) {  // <<<272, 1024>>>
    const int tid = threadIdx.x;

    __shared__ union {
        struct {                                   // tables path
            int            sc[256];
            unsigned short sMask[MAXREG];
            float          sH[NK][NZ];
            int            s_cnt;
        } t;
        struct {                                   // cross path
            float zA[4][NZ];
        } x;
    } sh;

    if (blockIdx.x < NCH) {
        const int c = blockIdx.x;
        unsigned w[4]; int pc = 0;
        if (tid < 256) {
            #pragma unroll
            for (int j = 0; j < 4; j++) {
                w[j] = g_seen[c][tid * 4 + j];
                g_seen[c][tid * 4 + j] = 0u;               // self-clean for next launch
                pc += __popc(w[j]);
            }
            sh.t.sc[tid] = pc;
        }
        const int base = (c & 1) * NK;                     // even ch -> H rows 0..14, odd -> 15..29
        for (int i = tid; i < NK * NZ; i += 1024)
            sh.t.sH[i >> 8][i & 255] = H[(base + (i >> 8)) * NZ + (i & 255)];
        __syncthreads();
        for (int off = 1; off < 256; off <<= 1) {          // Hillis-Steele inclusive scan
            int v = 0;
            if (tid < 256 && tid >= off) v = sh.t.sc[tid - off];
            __syncthreads();
            if (tid < 256) sh.t.sc[tid] += v;
            __syncthreads();
        }
        if (tid < 256) {
            int id = sh.t.sc[tid] - pc;                    // exclusive prefix (ascending-mask order)
            if (tid == 255) { g_cnt[c] = min(sh.t.sc[255], MAXREG); sh.t.s_cnt = min(sh.t.sc[255], MAXREG); }
            #pragma unroll
            for (int j = 0; j < 4; j++) {
                const int word = tid * 4 + j;
                unsigned ww = w[j];
                const unsigned mb = (unsigned)word << 5;
                while (ww) {
                    int bb = __ffs(ww) - 1; ww &= ww - 1;
                    if (id < MAXREG) {
                        unsigned short mask = (unsigned short)(mb | (unsigned)bb);
                        g_rmap[c][mask] = (unsigned char)id;
                        sh.t.sMask[id] = mask;
                    }
                    id++;
                }
            }
        }
        __syncthreads();

        const int cnt = sh.t.s_cnt;
        const int col = tid & 255, grp = tid >> 8;         // 4-way row parallelism
        for (int r = grp; r < cnt; r += 4) {
            unsigned m = sh.t.sMask[r];
            float acc = 0.f;
            #pragma unroll
            for (int d = 0; d < NK; d++) {
                float hv = sh.t.sH[d][col];
                acc += ((m >> d) & 1) ? -hv : hv;
            }
            g_zreg[c][r][col] = acc;
        }

        __syncthreads();
        __threadfence();
        if (tid == 0) g_flag[c] = 1;
    } else {
        const int idx2 = blockIdx.x - NCH;                 // 0..255
        const int rAt = idx2 & 31;                         // 32 rA tiles of 4
        const int c8  = idx2 >> 5;                         // 8 pairs
        const int cA = 2 * c8, cB = cA + 1;

        if (tid == 0) {                                    // wait for this pair's tables blocks
            while (!(g_flag[cA] && g_flag[cB])) __nanosleep(64);
        }
        __syncthreads();                                   // acquire for the whole block

        const int nA = g_cnt[cA], nB = g_cnt[cB];
        const int rA0 = rAt * 4;
        if (rA0 >= nA) return;
        const int na = min(4, nA - rA0);
        for (int i = tid; i < 4 * NZ; i += 1024) {
            int rr = i >> 8, k = i & 255;
            sh.x.zA[rr][k] = (rr < na) ? g_zreg[cA][rA0 + rr][k] : 0.f;
        }
        __syncthreads();
        const int warp = tid >> 5, lane = tid & 31;        // 32 warps over rB
        for (int rB = warp; rB < nB; rB += 32) {
            const float* zb = &g_zreg[cB][rB][0];
            float zl[8];
            #pragma unroll
            for (int j = 0; j < 8; j++) zl[j] = zb[j * 32 + lane];
            #pragma unroll
            for (int i2 = 0; i2 < 4; i2++) {
                float best = __int_as_float(0xff800000);   // -inf
                int   bk = 0;
                #pragma unroll
                for (int j = 0; j < 8; j++) {
                    int k = j * 32 + lane;                 // ascending per lane
                    float v = sh.x.zA[i2][k] + zl[j];
                    if (v > best) { best = v; bk = k; }
                }
                #pragma unroll
                for (int off = 16; off; off >>= 1) {       // first-index-wins warp argmax
                    float ov = __shfl_down_sync(0xffffffffu, best, off);
                    int   ok = __shfl_down_sync(0xffffffffu, bk, off);
                    if (ov > best || (ov == best && ok < bk)) { best = ov; bk = ok; }
                }
                if (lane == 0 && i2 < na) g_cross[c8][rA0 + i2][rB] = (unsigned char)bk;
            }
        }
    }
}

// ================= K3: gather + log_softmax — 2 elements/thread for L2-gather MLP =======
#define K4_BLK 256
#define K4_THR 256
#define LUTPAD 12
#define K4_SMEM (8 * 256 * LUTPAD * 4)   // 98304 B -> 2 blocks/SM (512 thr/SM, 2x per-thread MLP)

__global__ void __launch_bounds__(K4_THR, 2) k_main(
    const float* __restrict__ LUT, float* __restrict__ out)
{
    extern __shared__ char dyn[];
    float* slut = (float*)dyn;

    const int tid = threadIdx.x;
    if (blockIdx.x == 0 && tid < NCH) g_flag[tid] = 0;   // reset flags for next launch
    for (int row = tid; row < 8 * 256; row += K4_THR) {
        #pragma unroll
        for (int j = 0; j < LUTPAD; j++)
            slut[row * LUTPAD + j] = (j < NCOUT) ? LUT[row * NCOUT + j] : 0.f;
    }
    __syncthreads();

    const int b0 = blockIdx.x * K4_THR + tid;            // 65536 threads, 2 elems each
    const int b1 = b0 + 65536;

    // stage both elements' mask words (4x LDG.128, independent)
    const uint4* mp0 = (const uint4*)&g_maskw[(size_t)b0 * 8];
    const uint4* mp1 = (const uint4*)&g_maskw[(size_t)b1 * 8];
    uint4 a0v = mp0[0], a1v = mp0[1], b0v = mp1[0], b1v = mp1[1];
    unsigned mwA[8] = {a0v.x, a0v.y, a0v.z, a0v.w, a1v.x, a1v.y, a1v.z, a1v.w};
    unsigned mwB[8] = {b0v.x, b0v.y, b0v.z, b0v.w, b1v.x, b1v.y, b1v.z, b1v.w};

    // 32 independent rmap u8 loads in flight
    int rA[NCH], rB[NCH];
    #pragma unroll
    for (int i = 0; i < 8; i++) {
        rA[2 * i]     = __ldg(&g_rmap[2 * i][mwA[i] & 0xffffu]);
        rA[2 * i + 1] = __ldg(&g_rmap[2 * i + 1][mwA[i] >> 16]);
        rB[2 * i]     = __ldg(&g_rmap[2 * i][mwB[i] & 0xffffu]);
        rB[2 * i + 1] = __ldg(&g_rmap[2 * i + 1][mwB[i] >> 16]);
    }

    // 16 independent cross u8 loads in flight
    int idxA[8], idxB[8];
    #pragma unroll
    for (int c8 = 0; c8 < 8; c8++) {
        idxA[c8] = __ldg(&g_cross[c8][rA[2 * c8]][rA[2 * c8 + 1]]);
        idxB[c8] = __ldg(&g_cross[c8][rB[2 * c8]][rB[2 * c8 + 1]]);
    }

    #pragma unroll
    for (int e = 0; e < 2; e++) {
        const int* idx = e ? idxB : idxA;
        const int  b   = e ? b1 : b0;

        float4 q0 = make_float4(0.f, 0.f, 0.f, 0.f), q1 = q0, q2 = q0;
        #pragma unroll
        for (int c8 = 0; c8 < 8; c8++) {
            const float4* p = (const float4*)&slut[(c8 * 256 + idx[c8]) * LUTPAD];
            float4 v0 = p[0], v1 = p[1], v2 = p[2];
            q0.x += v0.x; q0.y += v0.y; q0.z += v0.z; q0.w += v0.w;
            q1.x += v1.x; q1.y += v1.y; q1.z += v1.z; q1.w += v1.w;
            q2.x += v2.x; q2.y += v2.y;                  // lanes 10,11 are pad
        }
        float acc[NCOUT] = {q0.x, q0.y, q0.z, q0.w, q1.x, q1.y, q1.z, q1.w, q2.x, q2.y};

        float mx = acc[0];
        #pragma unroll
        for (int j = 1; j < NCOUT; j++) mx = fmaxf(mx, acc[j]);
        float s = 0.f;
        #pragma unroll
        for (int j = 0; j < NCOUT; j++) s += __expf(acc[j] - mx);
        float lg = __logf(s);

        float2* op = (float2*)(out + (size_t)b * NCOUT);
        #pragma unroll
        for (int j = 0; j < 5; j++)
            op[j] = make_float2((acc[2 * j] - mx) - lg, (acc[2 * j + 1] - mx) - lg);
    }
}

// ---------------- launch ----------------
extern "C" void kernel_launch(void* const* d_in, const int* in_sizes, int n_in,
                              void* d_out, int out_size) {
    const int*   x      = (const int*)d_in[0];
    const float* lenLUT = (const float*)d_in[1];
    const float* ipdLUT = (const float*)d_in[2];
    const float* S      = (const float*)d_in[3];
    const float* H      = (const float*)d_in[4];
    const float* T      = (const float*)d_in[5];
    const float* LUT    = (const float*)d_in[6];
    float*       out    = (float*)d_out;

    static int attr_done = 0;   // host-side, idempotent (set on the pre-capture correctness call)
    if (!attr_done) {
        cudaFuncSetAttribute(k_masks, cudaFuncAttributeMaxDynamicSharedMemorySize, K1_SMEM);
        cudaFuncSetAttribute(k_main,  cudaFuncAttributeMaxDynamicSharedMemorySize, K4_SMEM);
        attr_done = 1;
    }

    k_masks<<<K1_BLK, K1_THR, K1_SMEM>>>(x, lenLUT, ipdLUT, S, T);
    k_tc   <<<NCH + 256, 1024>>>(H);
    k_main <<<K4_BLK, K4_THR, K4_SMEM>>>(LUT, out);
}

// round 16
// speedup vs baseline: 1.0047x; 1.0047x over previous
#include <cuda_runtime.h>

#define BATCH 131072
#define NCH 16
#define NK 15
#define NZ 256
#define NCOUT 10
#define MAXREG 128
#define VOCAB 1024

typedef unsigned long long u64;

// ---------------- scratch (device globals; no allocation) ----------------
__device__ unsigned       g_seen[NCH][1024];     // built by k_masks, read+zeroed by k_tc tables blocks
__device__ unsigned char  g_rmap[NCH][32768];    // mask -> region id (observed entries valid this launch)
__device__ unsigned       g_maskw[BATCH * 8];    // packed masks: channel pair per u32
__device__ int            g_cnt[NCH];            // #distinct masks per channel (<=121)
__device__ float          g_zreg[NCH][MAXREG][NZ];       // per-region half z-row
__device__ unsigned char  g_cross[8][MAXREG][MAXREG];    // argmax index per (c8, rA, rB)
__device__ volatile int   g_flag[NCH];           // per-channel tables-done; reset by k_main

// ================= K1: sign masks — 2 elems/thread, phase-split filter, 3 blocks/SM =====
// Phase A: pairs 0-3 (channels 0-7) with a 32 KB filter; sync; clear; Phase B: pairs 4-7.
// Per phase only 4 mask words/element live -> fewer registers; STG.128 preserved per phase.
#define K1_BLK 256
#define K1_THR 256
#define K1_SMEM (8192 + 8192 + 1920 + 960 + 32768)   // 52032 B -> 3 blocks/SM (reg-capped 85)

__global__ void __launch_bounds__(K1_THR, 3) k_masks(
    const int* __restrict__ x, const float* __restrict__ lenLUT,
    const float* __restrict__ ipdLUT, const float* __restrict__ S,
    const float* __restrict__ T)
{
    extern __shared__ char dyn[];
    float2*     sLen = (float2*)dyn;                     // 8 KB
    float2*     sIpd = (float2*)(dyn + 8192);            // 8 KB
    ulonglong2* sSP  = (ulonglong2*)(dyn + 16384);       // 120 x {S0p, S1p}  (1920 B)
    u64*        sC   = (u64*)(dyn + 16384 + 1920);       // 120 x packed (-T-1e-4) (960 B)
    unsigned*   filt = (unsigned*)(dyn + 16384 + 2880);  // 32 KB filter for 8 channels/phase

    const int tid = threadIdx.x;
    for (int i = tid; i < VOCAB; i += K1_THR) {
        sLen[i] = ((const float2*)lenLUT)[i];
        sIpd[i] = ((const float2*)ipdLUT)[i];
    }
    if (tid < 120) {                                     // pack per-pair plane constants
        int i = tid / NK, k = tid % NK;
        int cA = 2 * i, cB = 2 * i + 1;
        u64 s0 = ((u64)__float_as_uint(S[cB * 30 + k])      << 32) | __float_as_uint(S[cA * 30 + k]);
        u64 s1 = ((u64)__float_as_uint(S[cB * 30 + 15 + k]) << 32) | __float_as_uint(S[cA * 30 + 15 + k]);
        float cAv = -T[cA * NK + k] - 1e-4f;
        float cBv = -T[cB * NK + k] - 1e-4f;
        sSP[tid] = make_ulonglong2(s0, s1);
        sC[tid]  = ((u64)__float_as_uint(cBv) << 32) | __float_as_uint(cAv);
    }
    for (int i = tid; i < 8 * 1024; i += K1_THR) filt[i] = 0u;
    __syncthreads();

    const int b0 = blockIdx.x * K1_THR + tid;            // 65536 threads, 2 elems each
    const int b1 = b0 + 65536;
    const int4* xp0 = (const int4*)x + (size_t)b0 * 8;
    const int4* xp1 = (const int4*)x + (size_t)b1 * 8;
    uint4* mp0 = (uint4*)&g_maskw[(size_t)b0 * 8];
    uint4* mp1 = (uint4*)&g_maskw[(size_t)b1 * 8];

    #pragma unroll
    for (int phase = 0; phase < 2; phase++) {
        unsigned w0[4], w1[4];
        #pragma unroll
        for (int ii = 0; ii < 4; ii++) {
            const int i = phase * 4 + ii;                // pair index 0..7
            int4 xv0 = __ldg(&xp0[i]);
            int4 xv1 = __ldg(&xp1[i]);

            float2 lA0 = sLen[xv0.x], pA0 = sIpd[xv0.y];
            float2 lB0 = sLen[xv0.z], pB0 = sIpd[xv0.w];
            float2 lA1 = sLen[xv1.x], pA1 = sIpd[xv1.y];
            float2 lB1 = sLen[xv1.z], pB1 = sIpd[xv1.w];

            u64 e0p0, e1p0, e0p1, e1p1;
            {
                float a = lA0.x + pA0.x, b = lB0.x + pB0.x;
                asm("mov.b64 %0, {%1, %2};" : "=l"(e0p0) : "f"(a), "f"(b));
                float c = lA0.y + pA0.y, d = lB0.y + pB0.y;
                asm("mov.b64 %0, {%1, %2};" : "=l"(e1p0) : "f"(c), "f"(d));
                float e = lA1.x + pA1.x, f = lB1.x + pB1.x;
                asm("mov.b64 %0, {%1, %2};" : "=l"(e0p1) : "f"(e), "f"(f));
                float g = lA1.y + pA1.y, h = lB1.y + pB1.y;
                asm("mov.b64 %0, {%1, %2};" : "=l"(e1p1) : "f"(g), "f"(h));
            }

            unsigned pair0 = 0, pair1 = 0;
            #pragma unroll
            for (int k = 0; k < NK; k++) {
                ulonglong2 sp = sSP[i * NK + k];         // LDS.128: S0p, S1p
                u64        cc = sC[i * NK + k];          // LDS.64
                u64 t0, y0, t1, y1;
                asm("fma.rn.f32x2 %0, %1, %2, %3;" : "=l"(t0) : "l"(e0p0), "l"(sp.x), "l"(cc));
                asm("fma.rn.f32x2 %0, %1, %2, %3;" : "=l"(t1) : "l"(e0p1), "l"(sp.x), "l"(cc));
                asm("fma.rn.f32x2 %0, %1, %2, %3;" : "=l"(y0) : "l"(e1p0), "l"(sp.y), "l"(t0));
                asm("fma.rn.f32x2 %0, %1, %2, %3;" : "=l"(y1) : "l"(e1p1), "l"(sp.y), "l"(t1));
                unsigned lo0 = (unsigned)y0, hi0 = (unsigned)(y0 >> 32);
                unsigned lo1 = (unsigned)y1, hi1 = (unsigned)(y1 >> 32);
                pair0 |= ((lo0 >> 31) << k) | ((hi0 >> 31) << (16 + k));  // bit set <=> y<0
                pair1 |= ((lo1 >> 31) << k) | ((hi1 >> 31) << (16 + k));
            }
            w0[ii] = pair0;
            w1[ii] = pair1;

            // inline observation (block filter, this phase's 8 channels -> rare global atomic)
            #pragma unroll
            for (int h2 = 0; h2 < 2; h2++) {
                unsigned m0 = (pair0 >> (16 * h2)) & 0xffffu;
                unsigned m1 = (pair1 >> (16 * h2)) & 0xffffu;
                const int c  = 2 * i + h2;               // global channel
                const int cl = c - phase * 8;            // filter-local channel 0..7
                unsigned wd0 = cl * 1024 + (m0 >> 5), bt0 = 1u << (m0 & 31);
                if (!(filt[wd0] & bt0)) {
                    unsigned old = atomicOr(&filt[wd0], bt0);
                    if (!(old & bt0)) atomicOr((unsigned*)&g_seen[c][m0 >> 5], bt0);
                }
                unsigned wd1 = cl * 1024 + (m1 >> 5), bt1 = 1u << (m1 & 31);
                if (!(filt[wd1] & bt1)) {
                    unsigned old = atomicOr(&filt[wd1], bt1);
                    if (!(old & bt1)) atomicOr((unsigned*)&g_seen[c][m1 >> 5], bt1);
                }
            }
        }
        mp0[phase] = make_uint4(w0[0], w0[1], w0[2], w0[3]);
        mp1[phase] = make_uint4(w1[0], w1[1], w1[2], w1[3]);

        if (phase == 0) {                                // clear filter for channels 8-15
            __syncthreads();
            for (int i = tid; i < 8 * 1024; i += K1_THR) filt[i] = 0u;
            __syncthreads();
        }
    }
}

// ================= K2: fused tables + cross (R13, unchanged) =================
__global__ void __launch_bounds__(1024, 2) k_tc(const float* __restrict__ H) {  // <<<272, 1024>>>
    const int tid = threadIdx.x;

    __shared__ union {
        struct {                                   // tables path
            int            sc[256];
            unsigned short sMask[MAXREG];
            float          sH[NK][NZ];
            int            s_cnt;
        } t;
        struct {                                   // cross path
            float zA[4][NZ];
        } x;
    } sh;

    if (blockIdx.x < NCH) {
        const int c = blockIdx.x;
        unsigned w[4]; int pc = 0;
        if (tid < 256) {
            #pragma unroll
            for (int j = 0; j < 4; j++) {
                w[j] = g_seen[c][tid * 4 + j];
                g_seen[c][tid * 4 + j] = 0u;               // self-clean for next launch
                pc += __popc(w[j]);
            }
            sh.t.sc[tid] = pc;
        }
        const int base = (c & 1) * NK;                     // even ch -> H rows 0..14, odd -> 15..29
        for (int i = tid; i < NK * NZ; i += 1024)
            sh.t.sH[i >> 8][i & 255] = H[(base + (i >> 8)) * NZ + (i & 255)];
        __syncthreads();
        for (int off = 1; off < 256; off <<= 1) {          // Hillis-Steele inclusive scan
            int v = 0;
            if (tid < 256 && tid >= off) v = sh.t.sc[tid - off];
            __syncthreads();
            if (tid < 256) sh.t.sc[tid] += v;
            __syncthreads();
        }
        if (tid < 256) {
            int id = sh.t.sc[tid] - pc;                    // exclusive prefix (ascending-mask order)
            if (tid == 255) { g_cnt[c] = min(sh.t.sc[255], MAXREG); sh.t.s_cnt = min(sh.t.sc[255], MAXREG); }
            #pragma unroll
            for (int j = 0; j < 4; j++) {
                const int word = tid * 4 + j;
                unsigned ww = w[j];
                const unsigned mb = (unsigned)word << 5;
                while (ww) {
                    int bb = __ffs(ww) - 1; ww &= ww - 1;
                    if (id < MAXREG) {
                        unsigned short mask = (unsigned short)(mb | (unsigned)bb);
                        g_rmap[c][mask] = (unsigned char)id;
                        sh.t.sMask[id] = mask;
                    }
                    id++;
                }
            }
        }
        __syncthreads();

        const int cnt = sh.t.s_cnt;
        const int col = tid & 255, grp = tid >> 8;         // 4-way row parallelism
        for (int r = grp; r < cnt; r += 4) {
            unsigned m = sh.t.sMask[r];
            float acc = 0.f;
            #pragma unroll
            for (int d = 0; d < NK; d++) {
                float hv = sh.t.sH[d][col];
                acc += ((m >> d) & 1) ? -hv : hv;
            }
            g_zreg[c][r][col] = acc;
        }

        __syncthreads();
        __threadfence();
        if (tid == 0) g_flag[c] = 1;
    } else {
        const int idx2 = blockIdx.x - NCH;                 // 0..255
        const int rAt = idx2 & 31;                         // 32 rA tiles of 4
        const int c8  = idx2 >> 5;                         // 8 pairs
        const int cA = 2 * c8, cB = cA + 1;

        if (tid == 0) {                                    // wait for this pair's tables blocks
            while (!(g_flag[cA] && g_flag[cB])) __nanosleep(64);
        }
        __syncthreads();                                   // acquire for the whole block

        const int nA = g_cnt[cA], nB = g_cnt[cB];
        const int rA0 = rAt * 4;
        if (rA0 >= nA) return;
        const int na = min(4, nA - rA0);
        for (int i = tid; i < 4 * NZ; i += 1024) {
            int rr = i >> 8, k = i & 255;
            sh.x.zA[rr][k] = (rr < na) ? g_zreg[cA][rA0 + rr][k] : 0.f;
        }
        __syncthreads();
        const int warp = tid >> 5, lane = tid & 31;        // 32 warps over rB
        for (int rB = warp; rB < nB; rB += 32) {
            const float* zb = &g_zreg[cB][rB][0];
            float zl[8];
            #pragma unroll
            for (int j = 0; j < 8; j++) zl[j] = zb[j * 32 + lane];
            #pragma unroll
            for (int i2 = 0; i2 < 4; i2++) {
                float best = __int_as_float(0xff800000);   // -inf
                int   bk = 0;
                #pragma unroll
                for (int j = 0; j < 8; j++) {
                    int k = j * 32 + lane;                 // ascending per lane
                    float v = sh.x.zA[i2][k] + zl[j];
                    if (v > best) { best = v; bk = k; }
                }
                #pragma unroll
                for (int off = 16; off; off >>= 1) {       // first-index-wins warp argmax
                    float ov = __shfl_down_sync(0xffffffffu, best, off);
                    int   ok = __shfl_down_sync(0xffffffffu, bk, off);
                    if (ov > best || (ov == best && ok < bk)) { best = ov; bk = ok; }
                }
                if (lane == 0 && i2 < na) g_cross[c8][rA0 + i2][rB] = (unsigned char)bk;
            }
        }
    }
}

// ================= K3: gather + log_softmax — 2 elements/thread (R14) =================
#define K4_BLK 256
#define K4_THR 256
#define LUTPAD 12
#define K4_SMEM (8 * 256 * LUTPAD * 4)   // 98304 B -> 2 blocks/SM

__global__ void __launch_bounds__(K4_THR, 2) k_main(
    const float* __restrict__ LUT, float* __restrict__ out)
{
    extern __shared__ char dyn[];
    float* slut = (float*)dyn;

    const int tid = threadIdx.x;
    if (blockIdx.x == 0 && tid < NCH) g_flag[tid] = 0;   // reset flags for next launch
    for (int row = tid; row < 8 * 256; row += K4_THR) {
        #pragma unroll
        for (int j = 0; j < LUTPAD; j++)
            slut[row * LUTPAD + j] = (j < NCOUT) ? LUT[row * NCOUT + j] : 0.f;
    }
    __syncthreads();

    const int b0 = blockIdx.x * K4_THR + tid;            // 65536 threads, 2 elems each
    const int b1 = b0 + 65536;

    const uint4* mp0 = (const uint4*)&g_maskw[(size_t)b0 * 8];
    const uint4* mp1 = (const uint4*)&g_maskw[(size_t)b1 * 8];
    uint4 a0v = mp0[0], a1v = mp0[1], b0v = mp1[0], b1v = mp1[1];
    unsigned mwA[8] = {a0v.x, a0v.y, a0v.z, a0v.w, a1v.x, a1v.y, a1v.z, a1v.w};
    unsigned mwB[8] = {b0v.x, b0v.y, b0v.z, b0v.w, b1v.x, b1v.y, b1v.z, b1v.w};

    int rA[NCH], rB[NCH];
    #pragma unroll
    for (int i = 0; i < 8; i++) {                        // 32 independent rmap u8 loads
        rA[2 * i]     = __ldg(&g_rmap[2 * i][mwA[i] & 0xffffu]);
        rA[2 * i + 1] = __ldg(&g_rmap[2 * i + 1][mwA[i] >> 16]);
        rB[2 * i]     = __ldg(&g_rmap[2 * i][mwB[i] & 0xffffu]);
        rB[2 * i + 1] = __ldg(&g_rmap[2 * i + 1][mwB[i] >> 16]);
    }

    int idxA[8], idxB[8];
    #pragma unroll
    for (int c8 = 0; c8 < 8; c8++) {                     // 16 independent cross u8 loads
        idxA[c8] = __ldg(&g_cross[c8][rA[2 * c8]][rA[2 * c8 + 1]]);
        idxB[c8] = __ldg(&g_cross[c8][rB[2 * c8]][rB[2 * c8 + 1]]);
    }

    #pragma unroll
    for (int e = 0; e < 2; e++) {
        const int* idx = e ? idxB : idxA;
        const int  b   = e ? b1 : b0;

        float4 q0 = make_float4(0.f, 0.f, 0.f, 0.f), q1 = q0, q2 = q0;
        #pragma unroll
        for (int c8 = 0; c8 < 8; c8++) {
            const float4* p = (const float4*)&slut[(c8 * 256 + idx[c8]) * LUTPAD];
            float4 v0 = p[0], v1 = p[1], v2 = p[2];
            q0.x += v0.x; q0.y += v0.y; q0.z += v0.z; q0.w += v0.w;
            q1.x += v1.x; q1.y += v1.y; q1.z += v1.z; q1.w += v1.w;
            q2.x += v2.x; q2.y += v2.y;                  // lanes 10,11 are pad
        }
        float acc[NCOUT] = {q0.x, q0.y, q0.z, q0.w, q1.x, q1.y, q1.z, q1.w, q2.x, q2.y};

        float mx = acc[0];
        #pragma unroll
        for (int j = 1; j < NCOUT; j++) mx = fmaxf(mx, acc[j]);
        float s = 0.f;
        #pragma unroll
        for (int j = 0; j < NCOUT; j++) s += __expf(acc[j] - mx);
        float lg = __logf(s);

        float2* op = (float2*)(out + (size_t)b * NCOUT);
        #pragma unroll
        for (int j = 0; j < 5; j++)
            op[j] = make_float2((acc[2 * j] - mx) - lg, (acc[2 * j + 1] - mx) - lg);
    }
}

// ---------------- launch ----------------
extern "C" void kernel_launch(void* const* d_in, const int* in_sizes, int n_in,
                              void* d_out, int out_size) {
    const int*   x      = (const int*)d_in[0];
    const float* lenLUT = (const float*)d_in[1];
    const float* ipdLUT = (const float*)d_in[2];
    const float* S      = (const float*)d_in[3];
    const float* H      = (const float*)d_in[4];
    const float* T      = (const float*)d_in[5];
    const float* LUT    = (const float*)d_in[6];
    float*       out    = (float*)d_out;

    static int attr_done = 0;   // host-side, idempotent (set on the pre-capture correctness call)
    if (!attr_done) {
        cudaFuncSetAttribute(k_masks, cudaFuncAttributeMaxDynamicSharedMemorySize, K1_SMEM);
        cudaFuncSetAttribute(k_main,  cudaFuncAttributeMaxDynamicSharedMemorySize, K4_SMEM);
        attr_done = 1;
    }

    k_masks<<<K1_BLK, K1_THR, K1_SMEM>>>(x, lenLUT, ipdLUT, S, T);
    k_tc   <<<NCH + 256, 1024>>>(H);
    k_main <<<K4_BLK, K4_THR, K4_SMEM>>>(LUT, out);
}